// round 13
// baseline (speedup 1.0000x reference)
#include <cuda_runtime.h>
#include <cuda_fp16.h>
#include <cstdint>
#include <cstddef>

// ---------------------------------------------------------------------------
// RWKV TimeMixing B=8,T=2048,C=1024
// GEMMs: fp16 HMMA, CTA 128x128, 8 warps @ 32x64, BK=64, 3-stage cp.async,
//        2 CTA/SM, z-fused k/v/r, compute-first stage body.
// WKV: chunk-parallel 3-pass scan, half2-vectorized local/output passes.
// ---------------------------------------------------------------------------
constexpr int B_ = 8;
constexpr int T_ = 2048;
constexpr int C_ = 1024;
constexpr int M_ = B_ * T_;                 // 16384
constexpr size_t BTC_ = (size_t)M_ * C_;
constexpr int BC_ = B_ * C_;                // 8192
constexpr int BC2_ = BC_ / 2;               // 4096
constexpr int C4_ = C_ / 4;
constexpr int NCH = 32;                     // scan chunks
constexpr int LCH = T_ / NCH;               // 64 steps per chunk

// Scratch (device globals; runtime allocation forbidden)
__device__ __align__(16) __half g_xk[BTC_];
__device__ __align__(16) __half g_xv[BTC_];
__device__ __align__(16) __half g_xr[BTC_];
__device__ __align__(16) __half g_kh[BTC_];
__device__ __align__(16) __half g_vh[BTC_];
__device__ __align__(16) __half g_rh[BTC_];
__device__ __align__(16) __half g_wk[C_ * C_];
__device__ __align__(16) __half g_wv[C_ * C_];
__device__ __align__(16) __half g_wr[C_ * C_];
__device__ __align__(16) __half g_wo[C_ * C_];
// chunk-scan intermediates
__device__ __align__(16) float g_locA[NCH * BC_];
__device__ __align__(16) float g_locB[NCH * BC_];
__device__ __align__(16) float g_locP[NCH * BC_];
__device__ __align__(16) float g_carA[NCH * BC_];
__device__ __align__(16) float g_carB[NCH * BC_];
__device__ __align__(16) float g_carP[NCH * BC_];
// rw (sigmoid(r)*wkv) reuses g_xk — xk dead after the k-GEMM.

// ---------------------------------------------------------------------------
// PTX helpers
// ---------------------------------------------------------------------------
__device__ __forceinline__ uint32_t s2u(const void* p) {
    return (uint32_t)__cvta_generic_to_shared(p);
}
__device__ __forceinline__ void cp16(uint32_t s, const void* g) {
    asm volatile("cp.async.cg.shared.global [%0], [%1], 16;" :: "r"(s), "l"(g));
}
__device__ __forceinline__ void cp_commit() {
    asm volatile("cp.async.commit_group;" ::: "memory");
}
__device__ __forceinline__ void cp_wait1() {
    asm volatile("cp.async.wait_group 1;" ::: "memory");
}
__device__ __forceinline__ void ldm4(uint32_t* r, uint32_t a) {
    asm volatile("ldmatrix.sync.aligned.m8n8.x4.shared.b16 {%0,%1,%2,%3}, [%4];"
                 : "=r"(r[0]), "=r"(r[1]), "=r"(r[2]), "=r"(r[3]) : "r"(a));
}
__device__ __forceinline__ void mma16816(float* c, const uint32_t* a,
                                         uint32_t b0, uint32_t b1) {
    asm volatile(
        "mma.sync.aligned.m16n8k16.row.col.f32.f16.f16.f32 "
        "{%0,%1,%2,%3}, {%4,%5,%6,%7}, {%8,%9}, {%0,%1,%2,%3};"
        : "+f"(c[0]), "+f"(c[1]), "+f"(c[2]), "+f"(c[3])
        : "r"(a[0]), "r"(a[1]), "r"(a[2]), "r"(a[3]), "r"(b0), "r"(b1));
}

// Swizzled byte offset inside a [rows x 64 fp16] tile (128B rows, 16B chunks).
__device__ __forceinline__ uint32_t swz8(int row, int ch) {
    return (uint32_t)(row * 128 + ((ch ^ (row & 7)) << 4));
}

// One WKV state-update step (log-stabilized), scalar.
__device__ __forceinline__ void wkv_step(float& aa, float& bb, float& pp,
                                         float kt, float vt, float w) {
    const float ww2 = pp + w;
    const float d2 = ww2 - kt;
    const float ed2 = __expf(-fabsf(d2));
    const float e1b = (d2 >= 0.0f) ? 1.0f : ed2;
    const float e2b = (d2 >= 0.0f) ? ed2 : 1.0f;
    aa = fmaf(e1b, aa, e2b * vt);
    bb = fmaf(e1b, bb, e2b);
    pp = (d2 >= 0.0f) ? ww2 : kt;
}
// wkv numerator/denominator ratio at current state.
__device__ __forceinline__ float wkv_val(float aa, float bb, float pp,
                                         float kt, float vt, float u) {
    const float ww = u + kt;
    const float d = pp - ww;
    const float ed = __expf(-fabsf(d));
    const float e1 = (d >= 0.0f) ? 1.0f : ed;
    const float e2 = (d >= 0.0f) ? ed : 1.0f;
    return __fdividef(fmaf(e1, aa, e2 * vt), fmaf(e1, bb, e2));
}

// ---------------------------------------------------------------------------
// 1) Weight transpose + fp16 (fused z=4): W[K,N] fp32 -> Wt[N,K] fp16
// ---------------------------------------------------------------------------
__global__ void wt_convert_kernel(const float* __restrict__ W0,
                                  const float* __restrict__ W1,
                                  const float* __restrict__ W2,
                                  const float* __restrict__ W3,
                                  __half* __restrict__ o0,
                                  __half* __restrict__ o1,
                                  __half* __restrict__ o2,
                                  __half* __restrict__ o3) {
    const float* W = (blockIdx.z == 0) ? W0 : (blockIdx.z == 1) ? W1
                     : (blockIdx.z == 2) ? W2 : W3;
    __half* o = (blockIdx.z == 0) ? o0 : (blockIdx.z == 1) ? o1
                : (blockIdx.z == 2) ? o2 : o3;
    __shared__ float tile[32][33];
    const int n0 = blockIdx.x * 32, k0 = blockIdx.y * 32;
    const int tx = threadIdx.x, ty = threadIdx.y;
    for (int i = ty; i < 32; i += 8)
        tile[i][tx] = W[(size_t)(k0 + i) * C_ + n0 + tx];
    __syncthreads();
    for (int i = ty; i < 32; i += 8)
        o[(size_t)(n0 + i) * C_ + k0 + tx] = __float2half(tile[tx][i]);
}

// ---------------------------------------------------------------------------
// 2) Token-shift + time-mix -> fp16 operands; also last_x output
// ---------------------------------------------------------------------------
__device__ __forceinline__ float4 mix4(float4 a, float4 xx, float4 m) {
    float4 r;
    r.x = fmaf(m.x, a.x - xx.x, xx.x);
    r.y = fmaf(m.y, a.y - xx.y, xx.y);
    r.z = fmaf(m.z, a.z - xx.z, xx.z);
    r.w = fmaf(m.w, a.w - xx.w, xx.w);
    return r;
}
__device__ __forceinline__ void st_h4(float4 v, __half* p, size_t e) {
    __half2 h0, h1;
    h0.x = __float2half(v.x); h0.y = __float2half(v.y);
    h1.x = __float2half(v.z); h1.y = __float2half(v.w);
    uint2 pack;
    pack.x = *reinterpret_cast<uint32_t*>(&h0);
    pack.y = *reinterpret_cast<uint32_t*>(&h1);
    *reinterpret_cast<uint2*>(p + e) = pack;
}

__global__ void mix_kernel(const float4* __restrict__ x,
                           const float4* __restrict__ last_x,
                           const float4* __restrict__ tmk,
                           const float4* __restrict__ tmv,
                           const float4* __restrict__ tmr,
                           float4* lastx_out) {
    size_t i = (size_t)blockIdx.x * blockDim.x + threadIdx.x;
    if (i >= BTC_ / 4) return;
    int c4 = (int)(i % C4_);
    size_t bt = i / C4_;
    int t = (int)(bt % T_);
    int b = (int)(bt / T_);

    float4 xc = x[i];
    float4 xx = (t == 0) ? last_x[(size_t)b * C4_ + c4] : x[i - C4_];
    size_t e = i * 4;
    st_h4(mix4(xc, xx, tmk[c4]), g_xk, e);
    st_h4(mix4(xc, xx, tmv[c4]), g_xv, e);
    st_h4(mix4(xc, xx, tmr[c4]), g_xr, e);

    if (t == T_ - 1 && lastx_out) lastx_out[(size_t)b * C4_ + c4] = xc;
}

// ---------------------------------------------------------------------------
// 3) HMMA GEMM: CTA 128x128, BK=64, 8 warps @ 32x64, 3-stage pipeline.
// ---------------------------------------------------------------------------
constexpr int BK_ = 64;
constexpr int KSTAGES = C_ / BK_;           // 16
constexpr int TILE_BYTES = 128 * BK_ * 2;   // 16384 per operand tile
constexpr int STAGE_BYTES = 2 * TILE_BYTES; // 32768 (A, B)
constexpr int NSTG = 3;
constexpr int SMEM_GEMM = NSTG * STAGE_BYTES;  // 98304

struct GemmArgs {
    const __half* A;
    const __half* W;
    float* Cf;    // fp32 output (if Ch == nullptr)
    __half* Ch;   // fp16 output (takes precedence)
};

__global__ __launch_bounds__(256, 2)
void gemm_kernel(GemmArgs ga0, GemmArgs ga1, GemmArgs ga2) {
    const GemmArgs ga = (blockIdx.z == 0) ? ga0 : (blockIdx.z == 1) ? ga1 : ga2;
    extern __shared__ char smem[];
    const uint32_t sbase = s2u(smem);
    const int tid = threadIdx.x;
    const int lane = tid & 31;
    const int wid = tid >> 5;
    const int wm = wid >> 1;   // 0..3  (m offset 32*wm)
    const int wn = wid & 1;    // 0..1  (n offset 64*wn)
    const int bm = blockIdx.y * 128, bn = blockIdx.x * 128;

    const char* aG = (const char*)ga.A + (size_t)bm * 2048;
    const char* bG = (const char*)ga.W + (size_t)bn * 2048;

    auto load_stage = [&](int s) {
        const uint32_t sb = sbase + (s % NSTG) * STAGE_BYTES;
        const int kbyte = s * 128;  // 64 fp16 per stage
#pragma unroll
        for (int i = 0; i < 4; i++) {
            const int idx = tid + i * 256;  // 0..1023
            const int row = idx >> 3;
            const int ch = idx & 7;
            const uint32_t so = swz8(row, ch);
            const size_t go = (size_t)row * 2048 + kbyte + ch * 16;
            cp16(sb + so, aG + go);
            cp16(sb + TILE_BYTES + so, bG + go);
        }
        cp_commit();
    };

    float acc[2][8][4];
#pragma unroll
    for (int mt = 0; mt < 2; mt++)
#pragma unroll
        for (int nt = 0; nt < 8; nt++)
#pragma unroll
            for (int i = 0; i < 4; i++) acc[mt][nt][i] = 0.0f;

    load_stage(0);
    load_stage(1);

    const int lrow = lane & 15;
    const int hi = lane >> 4;

    auto do_ks = [&](uint32_t sb, int ks) {
        const int ch = ks * 2 + hi;
        uint32_t af[2][4], bf[4][4];
#pragma unroll
        for (int mt = 0; mt < 2; mt++)
            ldm4(af[mt], sb + swz8(wm * 32 + mt * 16 + lrow, ch));
#pragma unroll
        for (int p = 0; p < 4; p++)
            ldm4(bf[p], sb + TILE_BYTES + swz8(wn * 64 + p * 16 + lrow, ch));
#pragma unroll
        for (int mt = 0; mt < 2; mt++)
#pragma unroll
            for (int p = 0; p < 4; p++) {
                mma16816(acc[mt][2 * p], af[mt], bf[p][0], bf[p][2]);
                mma16816(acc[mt][2 * p + 1], af[mt], bf[p][1], bf[p][3]);
            }
    };

    for (int s = 0; s < KSTAGES; s++) {
        cp_wait1();
        __syncthreads();
        const uint32_t sb = sbase + (s % NSTG) * STAGE_BYTES;

        do_ks(sb, 0);  // compute first, then issue next-stage loads
        if (s + 2 < KSTAGES) load_stage(s + 2);
        else cp_commit();  // empty group keeps wait_group numbering exact
#pragma unroll
        for (int ks = 1; ks < 4; ks++) do_ks(sb, ks);
    }

    // Epilogue
    if (ga.Ch) {
#pragma unroll
        for (int mt = 0; mt < 2; mt++) {
            const int row0 = bm + wm * 32 + mt * 16 + (lane >> 2);
#pragma unroll
            for (int nt = 0; nt < 8; nt++) {
                const int col = bn + wn * 64 + nt * 8 + (lane & 3) * 2;
                float* c = acc[mt][nt];
                *reinterpret_cast<__half2*>(ga.Ch + (size_t)row0 * C_ + col) =
                    __floats2half2_rn(c[0], c[1]);
                *reinterpret_cast<__half2*>(ga.Ch + (size_t)(row0 + 8) * C_ + col) =
                    __floats2half2_rn(c[2], c[3]);
            }
        }
    } else {
#pragma unroll
        for (int mt = 0; mt < 2; mt++) {
            const int row0 = bm + wm * 32 + mt * 16 + (lane >> 2);
#pragma unroll
            for (int nt = 0; nt < 8; nt++) {
                const int col = bn + wn * 64 + nt * 8 + (lane & 3) * 2;
                float* c = acc[mt][nt];
                *reinterpret_cast<float2*>(ga.Cf + (size_t)row0 * C_ + col) =
                    make_float2(c[0], c[1]);
                *reinterpret_cast<float2*>(ga.Cf + (size_t)(row0 + 8) * C_ + col) =
                    make_float2(c[2], c[3]);
            }
        }
    }
}

// ---------------------------------------------------------------------------
// 4a) WKV local pass (half2): thread owns 2 adjacent channels of one chunk.
// ---------------------------------------------------------------------------
__global__ void wkv_local_kernel(const __half2* __restrict__ k2,
                                 const __half2* __restrict__ v2,
                                 const float* __restrict__ td) {
    const int idx = blockIdx.x * blockDim.x + threadIdx.x;
    const int lane2 = idx & (BC2_ - 1);     // 0..4095
    const int ch = idx >> 12;               // chunk id
    const int c2 = lane2 & (C_ / 2 - 1);    // 0..511
    const int b = lane2 >> 9;
    const float w0 = td[2 * c2], w1 = td[2 * c2 + 1];

    float aa0 = 0.0f, bb0 = 0.0f, pp0 = -1e38f;
    float aa1 = 0.0f, bb1 = 0.0f, pp1 = -1e38f;
    const size_t base2 =
        ((size_t)b * T_ * C_ + (size_t)ch * LCH * C_) / 2 + c2;

#pragma unroll 4
    for (int t = 0; t < LCH; t++) {
        const size_t off = base2 + (size_t)t * (C_ / 2);
        const __half2 kh = k2[off];
        const __half2 vh = v2[off];
        const float2 kf = __half22float2(kh);
        const float2 vf = __half22float2(vh);
        wkv_step(aa0, bb0, pp0, kf.x, vf.x, w0);
        wkv_step(aa1, bb1, pp1, kf.y, vf.y, w1);
    }
    const int o = ch * BC_ + b * C_ + 2 * c2;
    *reinterpret_cast<float2*>(g_locA + o) = make_float2(aa0, aa1);
    *reinterpret_cast<float2*>(g_locB + o) = make_float2(bb0, bb1);
    *reinterpret_cast<float2*>(g_locP + o) = make_float2(pp0, pp1);
}

// ---------------------------------------------------------------------------
// 4b) Carry combine: serial over NCH chunks per lane (scalar — cheap).
// ---------------------------------------------------------------------------
__global__ void wkv_carry_kernel(const float* __restrict__ aa0,
                                 const float* __restrict__ bb0,
                                 const float* __restrict__ pp0,
                                 const float* __restrict__ td,
                                 float* aa_out, float* bb_out, float* pp_out) {
    const int lane = blockIdx.x * blockDim.x + threadIdx.x;
    if (lane >= BC_) return;
    const int c = lane & (C_ - 1);
    const float wL = td[c] * (float)LCH;

    float ca = aa0[lane], cb = bb0[lane], cp = pp0[lane];
#pragma unroll 4
    for (int ch = 0; ch < NCH; ch++) {
        const int o = ch * BC_ + lane;
        g_carA[o] = ca;
        g_carB[o] = cb;
        g_carP[o] = cp;
        const float A = g_locA[o], Bv = g_locB[o], P = g_locP[o];
        const float cpd = cp + wL;
        const float np = fmaxf(cpd, P);
        const float ea = __expf(cpd - np);
        const float eb = __expf(P - np);
        ca = fmaf(ea, ca, eb * A);
        cb = fmaf(ea, cb, eb * Bv);
        cp = np;
    }
    if (aa_out) {
        aa_out[lane] = ca;
        bb_out[lane] = cb;
        pp_out[lane] = cp;
    }
}

// ---------------------------------------------------------------------------
// 4c) WKV output pass (half2): replay chunk from carry, emit rw fp16.
// ---------------------------------------------------------------------------
__global__ void wkv_out_kernel(const __half2* __restrict__ k2,
                               const __half2* __restrict__ v2,
                               const __half2* __restrict__ r2,
                               const float* __restrict__ tf,
                               const float* __restrict__ td,
                               __half2* __restrict__ rw2) {
    const int idx = blockIdx.x * blockDim.x + threadIdx.x;
    const int lane2 = idx & (BC2_ - 1);
    const int ch = idx >> 12;
    const int c2 = lane2 & (C_ / 2 - 1);
    const int b = lane2 >> 9;
    const float u0 = tf[2 * c2], u1 = tf[2 * c2 + 1];
    const float w0 = td[2 * c2], w1 = td[2 * c2 + 1];

    const int o = ch * BC_ + b * C_ + 2 * c2;
    const float2 ca = *reinterpret_cast<const float2*>(g_carA + o);
    const float2 cb = *reinterpret_cast<const float2*>(g_carB + o);
    const float2 cp = *reinterpret_cast<const float2*>(g_carP + o);
    float aa0 = ca.x, bb0 = cb.x, pp0 = cp.x;
    float aa1 = ca.y, bb1 = cb.y, pp1 = cp.y;

    const size_t base2 =
        ((size_t)b * T_ * C_ + (size_t)ch * LCH * C_) / 2 + c2;

#pragma unroll 4
    for (int t = 0; t < LCH; t++) {
        const size_t off = base2 + (size_t)t * (C_ / 2);
        const float2 kf = __half22float2(k2[off]);
        const float2 vf = __half22float2(v2[off]);
        const float2 rf = __half22float2(r2[off]);

        const float wkv0 = wkv_val(aa0, bb0, pp0, kf.x, vf.x, u0);
        const float wkv1 = wkv_val(aa1, bb1, pp1, kf.y, vf.y, u1);
        const float s0 = __fdividef(1.0f, 1.0f + __expf(-rf.x));
        const float s1 = __fdividef(1.0f, 1.0f + __expf(-rf.y));
        rw2[off] = __floats2half2_rn(s0 * wkv0, s1 * wkv1);

        wkv_step(aa0, bb0, pp0, kf.x, vf.x, w0);
        wkv_step(aa1, bb1, pp1, kf.y, vf.y, w1);
    }
}

// ---------------------------------------------------------------------------
// Launch
// ---------------------------------------------------------------------------
extern "C" void kernel_launch(void* const* d_in, const int* in_sizes, int n_in,
                              void* d_out, int out_size) {
    const float* x   = (const float*)d_in[0];
    const float* lx  = (const float*)d_in[1];
    const float* aa0 = (const float*)d_in[2];
    const float* bb0 = (const float*)d_in[3];
    const float* pp0 = (const float*)d_in[4];
    const float* tmk = (const float*)d_in[5];
    const float* tmv = (const float*)d_in[6];
    const float* tmr = (const float*)d_in[7];
    const float* tf  = (const float*)d_in[8];
    const float* td  = (const float*)d_in[9];
    const float* Wk  = (const float*)d_in[10];
    const float* Wv  = (const float*)d_in[11];
    const float* Wr  = (const float*)d_in[12];
    const float* Wo  = (const float*)d_in[13];

    float* out = (float*)d_out;
    const bool full = (size_t)out_size >= BTC_ + 4 * (size_t)BC_;
    float* lastx_o = full ? out + BTC_ : nullptr;
    float* aa_o    = full ? out + BTC_ + 1 * (size_t)BC_ : nullptr;
    float* bb_o    = full ? out + BTC_ + 2 * (size_t)BC_ : nullptr;
    float* pp_o    = full ? out + BTC_ + 3 * (size_t)BC_ : nullptr;

    cudaFuncSetAttribute(gemm_kernel,
                         cudaFuncAttributeMaxDynamicSharedMemorySize, SMEM_GEMM);

    __half *xk, *xv, *xr, *wk, *wv, *wr, *wo, *kb, *vb, *rb;
    cudaGetSymbolAddress((void**)&xk, g_xk);
    cudaGetSymbolAddress((void**)&xv, g_xv);
    cudaGetSymbolAddress((void**)&xr, g_xr);
    cudaGetSymbolAddress((void**)&wk, g_wk);
    cudaGetSymbolAddress((void**)&wv, g_wv);
    cudaGetSymbolAddress((void**)&wr, g_wr);
    cudaGetSymbolAddress((void**)&wo, g_wo);
    cudaGetSymbolAddress((void**)&kb, g_kh);
    cudaGetSymbolAddress((void**)&vb, g_vh);
    cudaGetSymbolAddress((void**)&rb, g_rh);

    // Weight transpose + fp16 (fused z=4)
    {
        dim3 g(C_ / 32, C_ / 32, 4), b(32, 8);
        wt_convert_kernel<<<g, b>>>(Wk, Wv, Wr, Wo, wk, wv, wr, wo);
    }

    // Token-shift mix -> fp16 (+ last_x output)
    {
        const size_t n4 = BTC_ / 4;
        const int threads = 256;
        const int blocks = (int)((n4 + threads - 1) / threads);
        mix_kernel<<<blocks, threads>>>(
            (const float4*)x, (const float4*)lx, (const float4*)tmk,
            (const float4*)tmv, (const float4*)tmr, (float4*)lastx_o);
    }

    // k, v, r projections (fused z=3), fp16 outputs
    {
        GemmArgs gk{xk, wk, nullptr, kb}, gv{xv, wv, nullptr, vb},
                 gr{xr, wr, nullptr, rb};
        dim3 grid(C_ / 128, M_ / 128, 3);  // (8, 128, 3)
        gemm_kernel<<<grid, 256, SMEM_GEMM>>>(gk, gv, gr);
    }

    // WKV chunk-parallel scan (half2 local/out)
    wkv_local_kernel<<<(NCH * BC2_) / 256, 256>>>(
        (const __half2*)kb, (const __half2*)vb, td);
    wkv_carry_kernel<<<BC_ / 256, 256>>>(aa0, bb0, pp0, td, aa_o, bb_o, pp_o);
    wkv_out_kernel<<<(NCH * BC2_) / 256, 256>>>(
        (const __half2*)kb, (const __half2*)vb, (const __half2*)rb, tf, td,
        (__half2*)xk);

    // Output projection (fp32 out)
    {
        GemmArgs go{xk, wo, out, nullptr};
        dim3 grid(C_ / 128, M_ / 128, 1);
        gemm_kernel<<<grid, 256, SMEM_GEMM>>>(go, go, go);
    }
}

// round 15
// speedup vs baseline: 1.0180x; 1.0180x over previous
#include <cuda_runtime.h>
#include <cuda_fp16.h>
#include <cstdint>
#include <cstddef>

// ---------------------------------------------------------------------------
// RWKV TimeMixing B=8,T=2048,C=1024
// GEMMs: fp16 HMMA, CTA 128x128, 8 warps @ 32x64, BK=64, 3-stage cp.async,
//        2 CTA/SM, z-fused k/v/r, compute-first stage body.
// WKV: chunk-parallel 3-pass scan (scalar lanes, NCH=64 for occupancy).
// ---------------------------------------------------------------------------
constexpr int B_ = 8;
constexpr int T_ = 2048;
constexpr int C_ = 1024;
constexpr int M_ = B_ * T_;                 // 16384
constexpr size_t BTC_ = (size_t)M_ * C_;
constexpr int BC_ = B_ * C_;                // 8192
constexpr int C4_ = C_ / 4;
constexpr int NCH = 64;                     // scan chunks
constexpr int LCH = T_ / NCH;               // 32 steps per chunk

// Scratch (device globals; runtime allocation forbidden)
__device__ __align__(16) __half g_xk[BTC_];
__device__ __align__(16) __half g_xv[BTC_];
__device__ __align__(16) __half g_xr[BTC_];
__device__ __align__(16) __half g_kh[BTC_];
__device__ __align__(16) __half g_vh[BTC_];
__device__ __align__(16) __half g_rh[BTC_];
__device__ __align__(16) __half g_wk[C_ * C_];
__device__ __align__(16) __half g_wv[C_ * C_];
__device__ __align__(16) __half g_wr[C_ * C_];
__device__ __align__(16) __half g_wo[C_ * C_];
// chunk-scan intermediates
__device__ float g_locA[NCH * BC_];
__device__ float g_locB[NCH * BC_];
__device__ float g_locP[NCH * BC_];
__device__ float g_carA[NCH * BC_];
__device__ float g_carB[NCH * BC_];
__device__ float g_carP[NCH * BC_];
// rw (sigmoid(r)*wkv) reuses g_xk — xk dead after the k-GEMM.

// ---------------------------------------------------------------------------
// PTX helpers
// ---------------------------------------------------------------------------
__device__ __forceinline__ uint32_t s2u(const void* p) {
    return (uint32_t)__cvta_generic_to_shared(p);
}
__device__ __forceinline__ void cp16(uint32_t s, const void* g) {
    asm volatile("cp.async.cg.shared.global [%0], [%1], 16;" :: "r"(s), "l"(g));
}
__device__ __forceinline__ void cp_commit() {
    asm volatile("cp.async.commit_group;" ::: "memory");
}
__device__ __forceinline__ void cp_wait1() {
    asm volatile("cp.async.wait_group 1;" ::: "memory");
}
__device__ __forceinline__ void ldm4(uint32_t* r, uint32_t a) {
    asm volatile("ldmatrix.sync.aligned.m8n8.x4.shared.b16 {%0,%1,%2,%3}, [%4];"
                 : "=r"(r[0]), "=r"(r[1]), "=r"(r[2]), "=r"(r[3]) : "r"(a));
}
__device__ __forceinline__ void mma16816(float* c, const uint32_t* a,
                                         uint32_t b0, uint32_t b1) {
    asm volatile(
        "mma.sync.aligned.m16n8k16.row.col.f32.f16.f16.f32 "
        "{%0,%1,%2,%3}, {%4,%5,%6,%7}, {%8,%9}, {%0,%1,%2,%3};"
        : "+f"(c[0]), "+f"(c[1]), "+f"(c[2]), "+f"(c[3])
        : "r"(a[0]), "r"(a[1]), "r"(a[2]), "r"(a[3]), "r"(b0), "r"(b1));
}

// Swizzled byte offset inside a [rows x 64 fp16] tile (128B rows, 16B chunks).
__device__ __forceinline__ uint32_t swz8(int row, int ch) {
    return (uint32_t)(row * 128 + ((ch ^ (row & 7)) << 4));
}

// ---------------------------------------------------------------------------
// 1) Weight transpose + fp16 (fused z=4): W[K,N] fp32 -> Wt[N,K] fp16
// ---------------------------------------------------------------------------
__global__ void wt_convert_kernel(const float* __restrict__ W0,
                                  const float* __restrict__ W1,
                                  const float* __restrict__ W2,
                                  const float* __restrict__ W3,
                                  __half* __restrict__ o0,
                                  __half* __restrict__ o1,
                                  __half* __restrict__ o2,
                                  __half* __restrict__ o3) {
    const float* W = (blockIdx.z == 0) ? W0 : (blockIdx.z == 1) ? W1
                     : (blockIdx.z == 2) ? W2 : W3;
    __half* o = (blockIdx.z == 0) ? o0 : (blockIdx.z == 1) ? o1
                : (blockIdx.z == 2) ? o2 : o3;
    __shared__ float tile[32][33];
    const int n0 = blockIdx.x * 32, k0 = blockIdx.y * 32;
    const int tx = threadIdx.x, ty = threadIdx.y;
    for (int i = ty; i < 32; i += 8)
        tile[i][tx] = W[(size_t)(k0 + i) * C_ + n0 + tx];
    __syncthreads();
    for (int i = ty; i < 32; i += 8)
        o[(size_t)(n0 + i) * C_ + k0 + tx] = __float2half(tile[tx][i]);
}

// ---------------------------------------------------------------------------
// 2) Token-shift + time-mix -> fp16 operands; also last_x output
// ---------------------------------------------------------------------------
__device__ __forceinline__ float4 mix4(float4 a, float4 xx, float4 m) {
    float4 r;
    r.x = fmaf(m.x, a.x - xx.x, xx.x);
    r.y = fmaf(m.y, a.y - xx.y, xx.y);
    r.z = fmaf(m.z, a.z - xx.z, xx.z);
    r.w = fmaf(m.w, a.w - xx.w, xx.w);
    return r;
}
__device__ __forceinline__ void st_h4(float4 v, __half* p, size_t e) {
    __half2 h0, h1;
    h0.x = __float2half(v.x); h0.y = __float2half(v.y);
    h1.x = __float2half(v.z); h1.y = __float2half(v.w);
    uint2 pack;
    pack.x = *reinterpret_cast<uint32_t*>(&h0);
    pack.y = *reinterpret_cast<uint32_t*>(&h1);
    *reinterpret_cast<uint2*>(p + e) = pack;
}

__global__ void mix_kernel(const float4* __restrict__ x,
                           const float4* __restrict__ last_x,
                           const float4* __restrict__ tmk,
                           const float4* __restrict__ tmv,
                           const float4* __restrict__ tmr,
                           float4* lastx_out) {
    size_t i = (size_t)blockIdx.x * blockDim.x + threadIdx.x;
    if (i >= BTC_ / 4) return;
    int c4 = (int)(i % C4_);
    size_t bt = i / C4_;
    int t = (int)(bt % T_);
    int b = (int)(bt / T_);

    float4 xc = x[i];
    float4 xx = (t == 0) ? last_x[(size_t)b * C4_ + c4] : x[i - C4_];
    size_t e = i * 4;
    st_h4(mix4(xc, xx, tmk[c4]), g_xk, e);
    st_h4(mix4(xc, xx, tmv[c4]), g_xv, e);
    st_h4(mix4(xc, xx, tmr[c4]), g_xr, e);

    if (t == T_ - 1 && lastx_out) lastx_out[(size_t)b * C4_ + c4] = xc;
}

// ---------------------------------------------------------------------------
// 3) HMMA GEMM: CTA 128x128, BK=64, 8 warps @ 32x64, 3-stage pipeline.
// ---------------------------------------------------------------------------
constexpr int BK_ = 64;
constexpr int KSTAGES = C_ / BK_;           // 16
constexpr int TILE_BYTES = 128 * BK_ * 2;   // 16384 per operand tile
constexpr int STAGE_BYTES = 2 * TILE_BYTES; // 32768 (A, B)
constexpr int NSTG = 3;
constexpr int SMEM_GEMM = NSTG * STAGE_BYTES;  // 98304

struct GemmArgs {
    const __half* A;
    const __half* W;
    float* Cf;    // fp32 output (if Ch == nullptr)
    __half* Ch;   // fp16 output (takes precedence)
};

__global__ __launch_bounds__(256, 2)
void gemm_kernel(GemmArgs ga0, GemmArgs ga1, GemmArgs ga2) {
    const GemmArgs ga = (blockIdx.z == 0) ? ga0 : (blockIdx.z == 1) ? ga1 : ga2;
    extern __shared__ char smem[];
    const uint32_t sbase = s2u(smem);
    const int tid = threadIdx.x;
    const int lane = tid & 31;
    const int wid = tid >> 5;
    const int wm = wid >> 1;   // 0..3  (m offset 32*wm)
    const int wn = wid & 1;    // 0..1  (n offset 64*wn)
    const int bm = blockIdx.y * 128, bn = blockIdx.x * 128;

    const char* aG = (const char*)ga.A + (size_t)bm * 2048;
    const char* bG = (const char*)ga.W + (size_t)bn * 2048;

    auto load_stage = [&](int s) {
        const uint32_t sb = sbase + (s % NSTG) * STAGE_BYTES;
        const int kbyte = s * 128;  // 64 fp16 per stage
#pragma unroll
        for (int i = 0; i < 4; i++) {
            const int idx = tid + i * 256;  // 0..1023
            const int row = idx >> 3;
            const int ch = idx & 7;
            const uint32_t so = swz8(row, ch);
            const size_t go = (size_t)row * 2048 + kbyte + ch * 16;
            cp16(sb + so, aG + go);
            cp16(sb + TILE_BYTES + so, bG + go);
        }
        cp_commit();
    };

    float acc[2][8][4];
#pragma unroll
    for (int mt = 0; mt < 2; mt++)
#pragma unroll
        for (int nt = 0; nt < 8; nt++)
#pragma unroll
            for (int i = 0; i < 4; i++) acc[mt][nt][i] = 0.0f;

    load_stage(0);
    load_stage(1);

    const int lrow = lane & 15;
    const int hi = lane >> 4;

    auto do_ks = [&](uint32_t sb, int ks) {
        const int ch = ks * 2 + hi;
        uint32_t af[2][4], bf[4][4];
#pragma unroll
        for (int mt = 0; mt < 2; mt++)
            ldm4(af[mt], sb + swz8(wm * 32 + mt * 16 + lrow, ch));
#pragma unroll
        for (int p = 0; p < 4; p++)
            ldm4(bf[p], sb + TILE_BYTES + swz8(wn * 64 + p * 16 + lrow, ch));
#pragma unroll
        for (int mt = 0; mt < 2; mt++)
#pragma unroll
            for (int p = 0; p < 4; p++) {
                mma16816(acc[mt][2 * p], af[mt], bf[p][0], bf[p][2]);
                mma16816(acc[mt][2 * p + 1], af[mt], bf[p][1], bf[p][3]);
            }
    };

    for (int s = 0; s < KSTAGES; s++) {
        cp_wait1();
        __syncthreads();
        const uint32_t sb = sbase + (s % NSTG) * STAGE_BYTES;

        do_ks(sb, 0);  // compute first, then issue next-stage loads
        if (s + 2 < KSTAGES) load_stage(s + 2);
        else cp_commit();  // empty group keeps wait_group numbering exact
#pragma unroll
        for (int ks = 1; ks < 4; ks++) do_ks(sb, ks);
    }

    // Epilogue
    if (ga.Ch) {
#pragma unroll
        for (int mt = 0; mt < 2; mt++) {
            const int row0 = bm + wm * 32 + mt * 16 + (lane >> 2);
#pragma unroll
            for (int nt = 0; nt < 8; nt++) {
                const int col = bn + wn * 64 + nt * 8 + (lane & 3) * 2;
                float* c = acc[mt][nt];
                *reinterpret_cast<__half2*>(ga.Ch + (size_t)row0 * C_ + col) =
                    __floats2half2_rn(c[0], c[1]);
                *reinterpret_cast<__half2*>(ga.Ch + (size_t)(row0 + 8) * C_ + col) =
                    __floats2half2_rn(c[2], c[3]);
            }
        }
    } else {
#pragma unroll
        for (int mt = 0; mt < 2; mt++) {
            const int row0 = bm + wm * 32 + mt * 16 + (lane >> 2);
#pragma unroll
            for (int nt = 0; nt < 8; nt++) {
                const int col = bn + wn * 64 + nt * 8 + (lane & 3) * 2;
                float* c = acc[mt][nt];
                *reinterpret_cast<float2*>(ga.Cf + (size_t)row0 * C_ + col) =
                    make_float2(c[0], c[1]);
                *reinterpret_cast<float2*>(ga.Cf + (size_t)(row0 + 8) * C_ + col) =
                    make_float2(c[2], c[3]);
            }
        }
    }
}

// ---------------------------------------------------------------------------
// 4a) WKV local pass: per-(lane, chunk) aggregate from zero state.
// ---------------------------------------------------------------------------
__global__ void wkv_local_kernel(const __half* __restrict__ k,
                                 const __half* __restrict__ v,
                                 const float* __restrict__ td) {
    const int idx = blockIdx.x * blockDim.x + threadIdx.x;
    const int lane = idx & (BC_ - 1);
    const int ch = idx >> 13;           // chunk id (BC_=8192=2^13)
    const int c = lane & (C_ - 1);
    const int b = lane >> 10;
    const float w = td[c];

    float aa = 0.0f, bb = 0.0f, pp = -1e38f;
    const size_t base = (size_t)b * T_ * C_ + (size_t)ch * LCH * C_ + c;

#pragma unroll 4
    for (int t = 0; t < LCH; t++) {
        const size_t off = base + (size_t)t * C_;
        const float kt = __half2float(k[off]);
        const float vt = __half2float(v[off]);
        const float ww2 = pp + w;
        const float d2 = ww2 - kt;
        const float ed2 = __expf(-fabsf(d2));
        const float e1b = (d2 >= 0.0f) ? 1.0f : ed2;
        const float e2b = (d2 >= 0.0f) ? ed2 : 1.0f;
        aa = fmaf(e1b, aa, e2b * vt);
        bb = fmaf(e1b, bb, e2b);
        pp = (d2 >= 0.0f) ? ww2 : kt;
    }
    g_locA[ch * BC_ + lane] = aa;
    g_locB[ch * BC_ + lane] = bb;
    g_locP[ch * BC_ + lane] = pp;
}

// ---------------------------------------------------------------------------
// 4b) Carry combine: serial over NCH chunks per lane.
// ---------------------------------------------------------------------------
__global__ void wkv_carry_kernel(const float* __restrict__ aa0,
                                 const float* __restrict__ bb0,
                                 const float* __restrict__ pp0,
                                 const float* __restrict__ td,
                                 float* aa_out, float* bb_out, float* pp_out) {
    const int lane = blockIdx.x * blockDim.x + threadIdx.x;
    if (lane >= BC_) return;
    const int c = lane & (C_ - 1);
    const float wL = td[c] * (float)LCH;

    float ca = aa0[lane], cb = bb0[lane], cp = pp0[lane];
#pragma unroll 4
    for (int ch = 0; ch < NCH; ch++) {
        const int o = ch * BC_ + lane;
        g_carA[o] = ca;
        g_carB[o] = cb;
        g_carP[o] = cp;
        const float A = g_locA[o], Bv = g_locB[o], P = g_locP[o];
        const float cpd = cp + wL;
        const float np = fmaxf(cpd, P);
        const float ea = __expf(cpd - np);
        const float eb = __expf(P - np);
        ca = fmaf(ea, ca, eb * A);
        cb = fmaf(ea, cb, eb * Bv);
        cp = np;
    }
    if (aa_out) {
        aa_out[lane] = ca;
        bb_out[lane] = cb;
        pp_out[lane] = cp;
    }
}

// ---------------------------------------------------------------------------
// 4c) WKV output pass: replay each chunk from its incoming carry.
// ---------------------------------------------------------------------------
__global__ void wkv_out_kernel(const __half* __restrict__ k,
                               const __half* __restrict__ v,
                               const __half* __restrict__ r,
                               const float* __restrict__ tf,
                               const float* __restrict__ td,
                               __half* __restrict__ rw) {
    const int idx = blockIdx.x * blockDim.x + threadIdx.x;
    const int lane = idx & (BC_ - 1);
    const int ch = idx >> 13;
    const int c = lane & (C_ - 1);
    const int b = lane >> 10;
    const float u = tf[c];
    const float w = td[c];

    const int o = ch * BC_ + lane;
    float aa = g_carA[o], bb = g_carB[o], pp = g_carP[o];
    const size_t base = (size_t)b * T_ * C_ + (size_t)ch * LCH * C_ + c;

#pragma unroll 4
    for (int t = 0; t < LCH; t++) {
        const size_t off = base + (size_t)t * C_;
        const float kt = __half2float(k[off]);
        const float vt = __half2float(v[off]);
        const float rt = __half2float(r[off]);

        const float ww = u + kt;
        const float d = pp - ww;
        const float ed = __expf(-fabsf(d));
        const float e1 = (d >= 0.0f) ? 1.0f : ed;
        const float e2 = (d >= 0.0f) ? ed : 1.0f;
        const float wkv = __fdividef(fmaf(e1, aa, e2 * vt), fmaf(e1, bb, e2));

        const float sig = __fdividef(1.0f, 1.0f + __expf(-rt));
        rw[off] = __float2half(sig * wkv);

        const float ww2 = pp + w;
        const float d2 = ww2 - kt;
        const float ed2 = __expf(-fabsf(d2));
        const float e1b = (d2 >= 0.0f) ? 1.0f : ed2;
        const float e2b = (d2 >= 0.0f) ? ed2 : 1.0f;
        aa = fmaf(e1b, aa, e2b * vt);
        bb = fmaf(e1b, bb, e2b);
        pp = (d2 >= 0.0f) ? ww2 : kt;
    }
}

// ---------------------------------------------------------------------------
// Launch
// ---------------------------------------------------------------------------
extern "C" void kernel_launch(void* const* d_in, const int* in_sizes, int n_in,
                              void* d_out, int out_size) {
    const float* x   = (const float*)d_in[0];
    const float* lx  = (const float*)d_in[1];
    const float* aa0 = (const float*)d_in[2];
    const float* bb0 = (const float*)d_in[3];
    const float* pp0 = (const float*)d_in[4];
    const float* tmk = (const float*)d_in[5];
    const float* tmv = (const float*)d_in[6];
    const float* tmr = (const float*)d_in[7];
    const float* tf  = (const float*)d_in[8];
    const float* td  = (const float*)d_in[9];
    const float* Wk  = (const float*)d_in[10];
    const float* Wv  = (const float*)d_in[11];
    const float* Wr  = (const float*)d_in[12];
    const float* Wo  = (const float*)d_in[13];

    float* out = (float*)d_out;
    const bool full = (size_t)out_size >= BTC_ + 4 * (size_t)BC_;
    float* lastx_o = full ? out + BTC_ : nullptr;
    float* aa_o    = full ? out + BTC_ + 1 * (size_t)BC_ : nullptr;
    float* bb_o    = full ? out + BTC_ + 2 * (size_t)BC_ : nullptr;
    float* pp_o    = full ? out + BTC_ + 3 * (size_t)BC_ : nullptr;

    cudaFuncSetAttribute(gemm_kernel,
                         cudaFuncAttributeMaxDynamicSharedMemorySize, SMEM_GEMM);

    __half *xk, *xv, *xr, *wk, *wv, *wr, *wo, *kb, *vb, *rb;
    cudaGetSymbolAddress((void**)&xk, g_xk);
    cudaGetSymbolAddress((void**)&xv, g_xv);
    cudaGetSymbolAddress((void**)&xr, g_xr);
    cudaGetSymbolAddress((void**)&wk, g_wk);
    cudaGetSymbolAddress((void**)&wv, g_wv);
    cudaGetSymbolAddress((void**)&wr, g_wr);
    cudaGetSymbolAddress((void**)&wo, g_wo);
    cudaGetSymbolAddress((void**)&kb, g_kh);
    cudaGetSymbolAddress((void**)&vb, g_vh);
    cudaGetSymbolAddress((void**)&rb, g_rh);

    // Weight transpose + fp16 (fused z=4)
    {
        dim3 g(C_ / 32, C_ / 32, 4), b(32, 8);
        wt_convert_kernel<<<g, b>>>(Wk, Wv, Wr, Wo, wk, wv, wr, wo);
    }

    // Token-shift mix -> fp16 (+ last_x output)
    {
        const size_t n4 = BTC_ / 4;
        const int threads = 256;
        const int blocks = (int)((n4 + threads - 1) / threads);
        mix_kernel<<<blocks, threads>>>(
            (const float4*)x, (const float4*)lx, (const float4*)tmk,
            (const float4*)tmv, (const float4*)tmr, (float4*)lastx_o);
    }

    // k, v, r projections (fused z=3), fp16 outputs
    {
        GemmArgs gk{xk, wk, nullptr, kb}, gv{xv, wv, nullptr, vb},
                 gr{xr, wr, nullptr, rb};
        dim3 grid(C_ / 128, M_ / 128, 3);  // (8, 128, 3)
        gemm_kernel<<<grid, 256, SMEM_GEMM>>>(gk, gv, gr);
    }

    // WKV chunk-parallel scan
    wkv_local_kernel<<<(NCH * BC_) / 256, 256>>>(kb, vb, td);
    wkv_carry_kernel<<<BC_ / 256, 256>>>(aa0, bb0, pp0, td, aa_o, bb_o, pp_o);
    wkv_out_kernel<<<(NCH * BC_) / 256, 256>>>(kb, vb, rb, tf, td, xk);

    // Output projection (fp32 out)
    {
        GemmArgs go{xk, wo, out, nullptr};
        dim3 grid(C_ / 128, M_ / 128, 1);
        gemm_kernel<<<grid, 256, SMEM_GEMM>>>(go, go, go);
    }
}

// round 16
// speedup vs baseline: 1.0605x; 1.0417x over previous
#include <cuda_runtime.h>
#include <cuda_fp16.h>
#include <cstdint>
#include <cstddef>

// ---------------------------------------------------------------------------
// RWKV TimeMixing B=8,T=2048,C=1024
// GEMMs: fp16 HMMA, CTA 128x128, 8 warps @ 32x64, BK=64, 3-stage cp.async.
// WKV: chunk-parallel 3-pass scan (NCH=32), local+carry overlapped with the
//      r-projection GEMM via a forked capture stream.
// ---------------------------------------------------------------------------
constexpr int B_ = 8;
constexpr int T_ = 2048;
constexpr int C_ = 1024;
constexpr int M_ = B_ * T_;                 // 16384
constexpr size_t BTC_ = (size_t)M_ * C_;
constexpr int BC_ = B_ * C_;                // 8192
constexpr int C4_ = C_ / 4;
constexpr int NCH = 32;                     // scan chunks
constexpr int LCH = T_ / NCH;               // 64 steps per chunk

// Scratch (device globals; runtime allocation forbidden)
__device__ __align__(16) __half g_xk[BTC_];
__device__ __align__(16) __half g_xv[BTC_];
__device__ __align__(16) __half g_xr[BTC_];
__device__ __align__(16) __half g_kh[BTC_];
__device__ __align__(16) __half g_vh[BTC_];
__device__ __align__(16) __half g_rh[BTC_];
__device__ __align__(16) __half g_wk[C_ * C_];
__device__ __align__(16) __half g_wv[C_ * C_];
__device__ __align__(16) __half g_wr[C_ * C_];
__device__ __align__(16) __half g_wo[C_ * C_];
// chunk-scan intermediates
__device__ float g_locA[NCH * BC_];
__device__ float g_locB[NCH * BC_];
__device__ float g_locP[NCH * BC_];
__device__ float g_carA[NCH * BC_];
__device__ float g_carB[NCH * BC_];
__device__ float g_carP[NCH * BC_];
// rw (sigmoid(r)*wkv) reuses g_xk — xk dead after the k-GEMM.

// ---------------------------------------------------------------------------
// PTX helpers
// ---------------------------------------------------------------------------
__device__ __forceinline__ uint32_t s2u(const void* p) {
    return (uint32_t)__cvta_generic_to_shared(p);
}
__device__ __forceinline__ void cp16(uint32_t s, const void* g) {
    asm volatile("cp.async.cg.shared.global [%0], [%1], 16;" :: "r"(s), "l"(g));
}
__device__ __forceinline__ void cp_commit() {
    asm volatile("cp.async.commit_group;" ::: "memory");
}
__device__ __forceinline__ void cp_wait1() {
    asm volatile("cp.async.wait_group 1;" ::: "memory");
}
__device__ __forceinline__ void ldm4(uint32_t* r, uint32_t a) {
    asm volatile("ldmatrix.sync.aligned.m8n8.x4.shared.b16 {%0,%1,%2,%3}, [%4];"
                 : "=r"(r[0]), "=r"(r[1]), "=r"(r[2]), "=r"(r[3]) : "r"(a));
}
__device__ __forceinline__ void mma16816(float* c, const uint32_t* a,
                                         uint32_t b0, uint32_t b1) {
    asm volatile(
        "mma.sync.aligned.m16n8k16.row.col.f32.f16.f16.f32 "
        "{%0,%1,%2,%3}, {%4,%5,%6,%7}, {%8,%9}, {%0,%1,%2,%3};"
        : "+f"(c[0]), "+f"(c[1]), "+f"(c[2]), "+f"(c[3])
        : "r"(a[0]), "r"(a[1]), "r"(a[2]), "r"(a[3]), "r"(b0), "r"(b1));
}

// Swizzled byte offset inside a [rows x 64 fp16] tile (128B rows, 16B chunks).
__device__ __forceinline__ uint32_t swz8(int row, int ch) {
    return (uint32_t)(row * 128 + ((ch ^ (row & 7)) << 4));
}

// ---------------------------------------------------------------------------
// 1) Weight transpose + fp16 (fused z=4): W[K,N] fp32 -> Wt[N,K] fp16
// ---------------------------------------------------------------------------
__global__ void wt_convert_kernel(const float* __restrict__ W0,
                                  const float* __restrict__ W1,
                                  const float* __restrict__ W2,
                                  const float* __restrict__ W3,
                                  __half* __restrict__ o0,
                                  __half* __restrict__ o1,
                                  __half* __restrict__ o2,
                                  __half* __restrict__ o3) {
    const float* W = (blockIdx.z == 0) ? W0 : (blockIdx.z == 1) ? W1
                     : (blockIdx.z == 2) ? W2 : W3;
    __half* o = (blockIdx.z == 0) ? o0 : (blockIdx.z == 1) ? o1
                : (blockIdx.z == 2) ? o2 : o3;
    __shared__ float tile[32][33];
    const int n0 = blockIdx.x * 32, k0 = blockIdx.y * 32;
    const int tx = threadIdx.x, ty = threadIdx.y;
    for (int i = ty; i < 32; i += 8)
        tile[i][tx] = W[(size_t)(k0 + i) * C_ + n0 + tx];
    __syncthreads();
    for (int i = ty; i < 32; i += 8)
        o[(size_t)(n0 + i) * C_ + k0 + tx] = __float2half(tile[tx][i]);
}

// ---------------------------------------------------------------------------
// 2) Token-shift + time-mix -> fp16 operands; also last_x output
// ---------------------------------------------------------------------------
__device__ __forceinline__ float4 mix4(float4 a, float4 xx, float4 m) {
    float4 r;
    r.x = fmaf(m.x, a.x - xx.x, xx.x);
    r.y = fmaf(m.y, a.y - xx.y, xx.y);
    r.z = fmaf(m.z, a.z - xx.z, xx.z);
    r.w = fmaf(m.w, a.w - xx.w, xx.w);
    return r;
}
__device__ __forceinline__ void st_h4(float4 v, __half* p, size_t e) {
    __half2 h0, h1;
    h0.x = __float2half(v.x); h0.y = __float2half(v.y);
    h1.x = __float2half(v.z); h1.y = __float2half(v.w);
    uint2 pack;
    pack.x = *reinterpret_cast<uint32_t*>(&h0);
    pack.y = *reinterpret_cast<uint32_t*>(&h1);
    *reinterpret_cast<uint2*>(p + e) = pack;
}

__global__ void mix_kernel(const float4* __restrict__ x,
                           const float4* __restrict__ last_x,
                           const float4* __restrict__ tmk,
                           const float4* __restrict__ tmv,
                           const float4* __restrict__ tmr,
                           float4* lastx_out) {
    size_t i = (size_t)blockIdx.x * blockDim.x + threadIdx.x;
    if (i >= BTC_ / 4) return;
    int c4 = (int)(i % C4_);
    size_t bt = i / C4_;
    int t = (int)(bt % T_);
    int b = (int)(bt / T_);

    float4 xc = x[i];
    float4 xx = (t == 0) ? last_x[(size_t)b * C4_ + c4] : x[i - C4_];
    size_t e = i * 4;
    st_h4(mix4(xc, xx, tmk[c4]), g_xk, e);
    st_h4(mix4(xc, xx, tmv[c4]), g_xv, e);
    st_h4(mix4(xc, xx, tmr[c4]), g_xr, e);

    if (t == T_ - 1 && lastx_out) lastx_out[(size_t)b * C4_ + c4] = xc;
}

// ---------------------------------------------------------------------------
// 3) HMMA GEMM: CTA 128x128, BK=64, 8 warps @ 32x64, 3-stage pipeline.
// ---------------------------------------------------------------------------
constexpr int BK_ = 64;
constexpr int KSTAGES = C_ / BK_;           // 16
constexpr int TILE_BYTES = 128 * BK_ * 2;   // 16384 per operand tile
constexpr int STAGE_BYTES = 2 * TILE_BYTES; // 32768 (A, B)
constexpr int NSTG = 3;
constexpr int SMEM_GEMM = NSTG * STAGE_BYTES;  // 98304

struct GemmArgs {
    const __half* A;
    const __half* W;
    float* Cf;    // fp32 output (if Ch == nullptr)
    __half* Ch;   // fp16 output (takes precedence)
};

__global__ __launch_bounds__(256, 2)
void gemm_kernel(GemmArgs ga0, GemmArgs ga1, GemmArgs ga2) {
    const GemmArgs ga = (blockIdx.z == 0) ? ga0 : (blockIdx.z == 1) ? ga1 : ga2;
    extern __shared__ char smem[];
    const uint32_t sbase = s2u(smem);
    const int tid = threadIdx.x;
    const int lane = tid & 31;
    const int wid = tid >> 5;
    const int wm = wid >> 1;   // 0..3  (m offset 32*wm)
    const int wn = wid & 1;    // 0..1  (n offset 64*wn)
    const int bm = blockIdx.y * 128, bn = blockIdx.x * 128;

    const char* aG = (const char*)ga.A + (size_t)bm * 2048;
    const char* bG = (const char*)ga.W + (size_t)bn * 2048;

    auto load_stage = [&](int s) {
        const uint32_t sb = sbase + (s % NSTG) * STAGE_BYTES;
        const int kbyte = s * 128;  // 64 fp16 per stage
#pragma unroll
        for (int i = 0; i < 4; i++) {
            const int idx = tid + i * 256;  // 0..1023
            const int row = idx >> 3;
            const int ch = idx & 7;
            const uint32_t so = swz8(row, ch);
            const size_t go = (size_t)row * 2048 + kbyte + ch * 16;
            cp16(sb + so, aG + go);
            cp16(sb + TILE_BYTES + so, bG + go);
        }
        cp_commit();
    };

    float acc[2][8][4];
#pragma unroll
    for (int mt = 0; mt < 2; mt++)
#pragma unroll
        for (int nt = 0; nt < 8; nt++)
#pragma unroll
            for (int i = 0; i < 4; i++) acc[mt][nt][i] = 0.0f;

    load_stage(0);
    load_stage(1);

    const int lrow = lane & 15;
    const int hi = lane >> 4;

    auto do_ks = [&](uint32_t sb, int ks) {
        const int ch = ks * 2 + hi;
        uint32_t af[2][4], bf[4][4];
#pragma unroll
        for (int mt = 0; mt < 2; mt++)
            ldm4(af[mt], sb + swz8(wm * 32 + mt * 16 + lrow, ch));
#pragma unroll
        for (int p = 0; p < 4; p++)
            ldm4(bf[p], sb + TILE_BYTES + swz8(wn * 64 + p * 16 + lrow, ch));
#pragma unroll
        for (int mt = 0; mt < 2; mt++)
#pragma unroll
            for (int p = 0; p < 4; p++) {
                mma16816(acc[mt][2 * p], af[mt], bf[p][0], bf[p][2]);
                mma16816(acc[mt][2 * p + 1], af[mt], bf[p][1], bf[p][3]);
            }
    };

    for (int s = 0; s < KSTAGES; s++) {
        cp_wait1();
        __syncthreads();
        const uint32_t sb = sbase + (s % NSTG) * STAGE_BYTES;

        do_ks(sb, 0);  // compute first, then issue next-stage loads
        if (s + 2 < KSTAGES) load_stage(s + 2);
        else cp_commit();  // empty group keeps wait_group numbering exact
#pragma unroll
        for (int ks = 1; ks < 4; ks++) do_ks(sb, ks);
    }

    // Epilogue
    if (ga.Ch) {
#pragma unroll
        for (int mt = 0; mt < 2; mt++) {
            const int row0 = bm + wm * 32 + mt * 16 + (lane >> 2);
#pragma unroll
            for (int nt = 0; nt < 8; nt++) {
                const int col = bn + wn * 64 + nt * 8 + (lane & 3) * 2;
                float* c = acc[mt][nt];
                *reinterpret_cast<__half2*>(ga.Ch + (size_t)row0 * C_ + col) =
                    __floats2half2_rn(c[0], c[1]);
                *reinterpret_cast<__half2*>(ga.Ch + (size_t)(row0 + 8) * C_ + col) =
                    __floats2half2_rn(c[2], c[3]);
            }
        }
    } else {
#pragma unroll
        for (int mt = 0; mt < 2; mt++) {
            const int row0 = bm + wm * 32 + mt * 16 + (lane >> 2);
#pragma unroll
            for (int nt = 0; nt < 8; nt++) {
                const int col = bn + wn * 64 + nt * 8 + (lane & 3) * 2;
                float* c = acc[mt][nt];
                *reinterpret_cast<float2*>(ga.Cf + (size_t)row0 * C_ + col) =
                    make_float2(c[0], c[1]);
                *reinterpret_cast<float2*>(ga.Cf + (size_t)(row0 + 8) * C_ + col) =
                    make_float2(c[2], c[3]);
            }
        }
    }
}

// ---------------------------------------------------------------------------
// 4a) WKV local pass: per-(lane, chunk) aggregate from zero state.
// ---------------------------------------------------------------------------
__global__ void wkv_local_kernel(const __half* __restrict__ k,
                                 const __half* __restrict__ v,
                                 const float* __restrict__ td) {
    const int idx = blockIdx.x * blockDim.x + threadIdx.x;
    const int lane = idx & (BC_ - 1);
    const int ch = idx >> 13;           // chunk id (BC_=8192=2^13)
    const int c = lane & (C_ - 1);
    const int b = lane >> 10;
    const float w = td[c];

    float aa = 0.0f, bb = 0.0f, pp = -1e38f;
    const size_t base = (size_t)b * T_ * C_ + (size_t)ch * LCH * C_ + c;

#pragma unroll 4
    for (int t = 0; t < LCH; t++) {
        const size_t off = base + (size_t)t * C_;
        const float kt = __half2float(k[off]);
        const float vt = __half2float(v[off]);
        const float ww2 = pp + w;
        const float d2 = ww2 - kt;
        const float ed2 = __expf(-fabsf(d2));
        const float e1b = (d2 >= 0.0f) ? 1.0f : ed2;
        const float e2b = (d2 >= 0.0f) ? ed2 : 1.0f;
        aa = fmaf(e1b, aa, e2b * vt);
        bb = fmaf(e1b, bb, e2b);
        pp = (d2 >= 0.0f) ? ww2 : kt;
    }
    g_locA[ch * BC_ + lane] = aa;
    g_locB[ch * BC_ + lane] = bb;
    g_locP[ch * BC_ + lane] = pp;
}

// ---------------------------------------------------------------------------
// 4b) Carry combine: serial over NCH chunks per lane.
// ---------------------------------------------------------------------------
__global__ void wkv_carry_kernel(const float* __restrict__ aa0,
                                 const float* __restrict__ bb0,
                                 const float* __restrict__ pp0,
                                 const float* __restrict__ td,
                                 float* aa_out, float* bb_out, float* pp_out) {
    const int lane = blockIdx.x * blockDim.x + threadIdx.x;
    if (lane >= BC_) return;
    const int c = lane & (C_ - 1);
    const float wL = td[c] * (float)LCH;

    float ca = aa0[lane], cb = bb0[lane], cp = pp0[lane];
#pragma unroll 4
    for (int ch = 0; ch < NCH; ch++) {
        const int o = ch * BC_ + lane;
        g_carA[o] = ca;
        g_carB[o] = cb;
        g_carP[o] = cp;
        const float A = g_locA[o], Bv = g_locB[o], P = g_locP[o];
        const float cpd = cp + wL;
        const float np = fmaxf(cpd, P);
        const float ea = __expf(cpd - np);
        const float eb = __expf(P - np);
        ca = fmaf(ea, ca, eb * A);
        cb = fmaf(ea, cb, eb * Bv);
        cp = np;
    }
    if (aa_out) {
        aa_out[lane] = ca;
        bb_out[lane] = cb;
        pp_out[lane] = cp;
    }
}

// ---------------------------------------------------------------------------
// 4c) WKV output pass: replay each chunk from its incoming carry.
// ---------------------------------------------------------------------------
__global__ void wkv_out_kernel(const __half* __restrict__ k,
                               const __half* __restrict__ v,
                               const __half* __restrict__ r,
                               const float* __restrict__ tf,
                               const float* __restrict__ td,
                               __half* __restrict__ rw) {
    const int idx = blockIdx.x * blockDim.x + threadIdx.x;
    const int lane = idx & (BC_ - 1);
    const int ch = idx >> 13;
    const int c = lane & (C_ - 1);
    const int b = lane >> 10;
    const float u = tf[c];
    const float w = td[c];

    const int o = ch * BC_ + lane;
    float aa = g_carA[o], bb = g_carB[o], pp = g_carP[o];
    const size_t base = (size_t)b * T_ * C_ + (size_t)ch * LCH * C_ + c;

#pragma unroll 4
    for (int t = 0; t < LCH; t++) {
        const size_t off = base + (size_t)t * C_;
        const float kt = __half2float(k[off]);
        const float vt = __half2float(v[off]);
        const float rt = __half2float(r[off]);

        const float ww = u + kt;
        const float d = pp - ww;
        const float ed = __expf(-fabsf(d));
        const float e1 = (d >= 0.0f) ? 1.0f : ed;
        const float e2 = (d >= 0.0f) ? ed : 1.0f;
        const float wkv = __fdividef(fmaf(e1, aa, e2 * vt), fmaf(e1, bb, e2));

        const float sig = __fdividef(1.0f, 1.0f + __expf(-rt));
        rw[off] = __float2half(sig * wkv);

        const float ww2 = pp + w;
        const float d2 = ww2 - kt;
        const float ed2 = __expf(-fabsf(d2));
        const float e1b = (d2 >= 0.0f) ? 1.0f : ed2;
        const float e2b = (d2 >= 0.0f) ? ed2 : 1.0f;
        aa = fmaf(e1b, aa, e2b * vt);
        bb = fmaf(e1b, bb, e2b);
        pp = (d2 >= 0.0f) ? ww2 : kt;
    }
}

// ---------------------------------------------------------------------------
// Launch — fork/join: scan local+carry on a side stream, overlapped with the
// r-projection GEMM on the main stream.
// ---------------------------------------------------------------------------
extern "C" void kernel_launch(void* const* d_in, const int* in_sizes, int n_in,
                              void* d_out, int out_size) {
    const float* x   = (const float*)d_in[0];
    const float* lx  = (const float*)d_in[1];
    const float* aa0 = (const float*)d_in[2];
    const float* bb0 = (const float*)d_in[3];
    const float* pp0 = (const float*)d_in[4];
    const float* tmk = (const float*)d_in[5];
    const float* tmv = (const float*)d_in[6];
    const float* tmr = (const float*)d_in[7];
    const float* tf  = (const float*)d_in[8];
    const float* td  = (const float*)d_in[9];
    const float* Wk  = (const float*)d_in[10];
    const float* Wv  = (const float*)d_in[11];
    const float* Wr  = (const float*)d_in[12];
    const float* Wo  = (const float*)d_in[13];

    float* out = (float*)d_out;
    const bool full = (size_t)out_size >= BTC_ + 4 * (size_t)BC_;
    float* lastx_o = full ? out + BTC_ : nullptr;
    float* aa_o    = full ? out + BTC_ + 1 * (size_t)BC_ : nullptr;
    float* bb_o    = full ? out + BTC_ + 2 * (size_t)BC_ : nullptr;
    float* pp_o    = full ? out + BTC_ + 3 * (size_t)BC_ : nullptr;

    cudaFuncSetAttribute(gemm_kernel,
                         cudaFuncAttributeMaxDynamicSharedMemorySize, SMEM_GEMM);

    // One-time host resources (created on the first, non-capturing call).
    static cudaStream_t s2 = nullptr;
    static cudaEvent_t ev_kv = nullptr;
    static cudaEvent_t ev_scan = nullptr;
    if (s2 == nullptr) {
        cudaStreamCreateWithFlags(&s2, cudaStreamNonBlocking);
        cudaEventCreateWithFlags(&ev_kv, cudaEventDisableTiming);
        cudaEventCreateWithFlags(&ev_scan, cudaEventDisableTiming);
    }

    __half *xk, *xv, *xr, *wk, *wv, *wr, *wo, *kb, *vb, *rb;
    cudaGetSymbolAddress((void**)&xk, g_xk);
    cudaGetSymbolAddress((void**)&xv, g_xv);
    cudaGetSymbolAddress((void**)&xr, g_xr);
    cudaGetSymbolAddress((void**)&wk, g_wk);
    cudaGetSymbolAddress((void**)&wv, g_wv);
    cudaGetSymbolAddress((void**)&wr, g_wr);
    cudaGetSymbolAddress((void**)&wo, g_wo);
    cudaGetSymbolAddress((void**)&kb, g_kh);
    cudaGetSymbolAddress((void**)&vb, g_vh);
    cudaGetSymbolAddress((void**)&rb, g_rh);

    // Weight transpose + fp16 (fused z=4)
    {
        dim3 g(C_ / 32, C_ / 32, 4), b(32, 8);
        wt_convert_kernel<<<g, b>>>(Wk, Wv, Wr, Wo, wk, wv, wr, wo);
    }

    // Token-shift mix -> fp16 (+ last_x output)
    {
        const size_t n4 = BTC_ / 4;
        const int threads = 256;
        const int blocks = (int)((n4 + threads - 1) / threads);
        mix_kernel<<<blocks, threads>>>(
            (const float4*)x, (const float4*)lx, (const float4*)tmk,
            (const float4*)tmv, (const float4*)tmr, (float4*)lastx_o);
    }

    // k, v projections (fused z=2), fp16 outputs
    {
        GemmArgs gk{xk, wk, nullptr, kb}, gv{xv, wv, nullptr, vb};
        dim3 grid(C_ / 128, M_ / 128, 2);  // (8, 128, 2)
        gemm_kernel<<<grid, 256, SMEM_GEMM>>>(gk, gv, gv);
    }
    cudaEventRecord(ev_kv, 0);

    // Fork: scan local + carry on s2 (needs only k, v)
    cudaStreamWaitEvent(s2, ev_kv, 0);
    wkv_local_kernel<<<(NCH * BC_) / 256, 256, 0, s2>>>(kb, vb, td);
    wkv_carry_kernel<<<BC_ / 256, 256, 0, s2>>>(aa0, bb0, pp0, td,
                                                aa_o, bb_o, pp_o);
    cudaEventRecord(ev_scan, s2);

    // Main: r projection, overlapped with the scan
    {
        GemmArgs gr{xr, wr, nullptr, rb};
        dim3 grid(C_ / 128, M_ / 128, 1);
        gemm_kernel<<<grid, 256, SMEM_GEMM>>>(gr, gr, gr);
    }

    // Join: output pass needs r (main, in-order) and carries (s2)
    cudaStreamWaitEvent(0, ev_scan, 0);
    wkv_out_kernel<<<(NCH * BC_) / 256, 256>>>(kb, vb, rb, tf, td, xk);

    // Output projection (fp32 out)
    {
        GemmArgs go{xk, wo, out, nullptr};
        dim3 grid(C_ / 128, M_ / 128, 1);
        gemm_kernel<<<grid, 256, SMEM_GEMM>>>(go, go, go);
    }
}